// round 1
// baseline (speedup 1.0000x reference)
#include <cuda_runtime.h>

#define H 64
#define TS 24
#define NSTORE 20000
#define NREG 2000
#define E_SS 640000
#define E_RS 160000
#define ALPHA 0.5f

// ---------------- device scratch (no allocations allowed) ----------------
__device__ float g_hs[NSTORE * H];
__device__ float g_hr[NREG * H];
__device__ float g_afwd[NSTORE * H];
__device__ float g_arev[NSTORE * H];
__device__ float g_ars[NSTORE * H];
__device__ int g_cntf[NSTORE];
__device__ int g_cntr[NSTORE];
__device__ int g_cntrs[NSTORE];

// ---------------- activations ----------------
__device__ __forceinline__ float sigf(float x) {
    x = fminf(fmaxf(x, -30.f), 30.f);
    return __fdividef(1.f, 1.f + __expf(-x));
}
__device__ __forceinline__ float tanh_fast(float x) {
    x = fminf(fmaxf(x, -15.f), 15.f);
    float e = __expf(-2.f * x);
    return __fdividef(1.f - e, 1.f + e);
}

// ---------------- zero kernel ----------------
__global__ void zero_kernel() {
    int i = blockIdx.x * blockDim.x + threadIdx.x;
    if (i < NSTORE * H) {
        g_afwd[i] = 0.f;
        g_arev[i] = 0.f;
        g_ars[i]  = 0.f;
    }
    if (i < NSTORE) {
        g_cntf[i] = 0;
        g_cntr[i] = 0;
        g_cntrs[i] = 0;
    }
}

// ---------------- LSTM kernel ----------------
// Block: 256 threads = 8 warps. Each warp owns 8 samples (64 samples/block).
// Lane l computes gates for hidden units u = l and u = l + 32.
// Whh staged in smem with row stride 68 (conflict-free LDS.128).
// h lives in smem (per-warp private rows, broadcast reads); c in registers.
#define LSTM_WSTRIDE 68
#define LSTM_SAMP 64
#define LSTM_THREADS 256
#define LSTM_SMEM_FLOATS (256 * LSTM_WSTRIDE + LSTM_SAMP * H + LSTM_SAMP * TS + 256 + 256)

__global__ __launch_bounds__(LSTM_THREADS, 2)
void lstm_kernel(const float* __restrict__ x, int N,
                 const float* __restrict__ Wih,
                 const float* __restrict__ Whh,
                 const float* __restrict__ bih,
                 const float* __restrict__ bhh,
                 float* __restrict__ hout)
{
    extern __shared__ float smem[];
    float* W_sm   = smem;                                 // 256 x 68
    float* h_sm   = W_sm + 256 * LSTM_WSTRIDE;            // 64 x 64
    float* x_sm   = h_sm + LSTM_SAMP * H;                 // 64 x 24
    float* win_sm = x_sm + LSTM_SAMP * TS;                // 256
    float* b_sm   = win_sm + 256;                         // 256

    const int tid = threadIdx.x;
    const int s0 = blockIdx.x * LSTM_SAMP;

    for (int i = tid; i < 256 * H; i += LSTM_THREADS) {
        int r = i >> 6, c = i & 63;
        W_sm[r * LSTM_WSTRIDE + c] = Whh[i];
    }
    for (int i = tid; i < 256; i += LSTM_THREADS) {
        win_sm[i] = Wih[i];            // Wih is [256][1]
        b_sm[i] = bih[i] + bhh[i];
    }
    for (int i = tid; i < LSTM_SAMP * TS; i += LSTM_THREADS) {
        long gi = (long)s0 * TS + i;
        x_sm[i] = (gi < (long)N * TS) ? x[gi] : 0.f;
    }
    for (int i = tid; i < LSTM_SAMP * H; i += LSTM_THREADS) h_sm[i] = 0.f;
    __syncthreads();

    const int warp = tid >> 5, lane = tid & 31;
    const int sbase = warp * 8;

    float c0[8], c1[8];
#pragma unroll
    for (int s = 0; s < 8; s++) { c0[s] = 0.f; c1[s] = 0.f; }

    for (int t = 0; t < TS; t++) {
        float xt[8];
#pragma unroll
        for (int s = 0; s < 8; s++) xt[s] = x_sm[(sbase + s) * TS + t];

        float hn0[8], hn1[8];
#pragma unroll
        for (int uh = 0; uh < 2; uh++) {
            const int u = lane + 32 * uh;
            float acc[8][4];
#pragma unroll
            for (int d = 0; d < 4; d++) {
                int j = u + 64 * d;
                float w = win_sm[j], b = b_sm[j];
#pragma unroll
                for (int s = 0; s < 8; s++) acc[s][d] = fmaf(xt[s], w, b);
            }
#pragma unroll 2
            for (int k4 = 0; k4 < H; k4 += 4) {
                float4 w4[4];
#pragma unroll
                for (int d = 0; d < 4; d++)
                    w4[d] = *(const float4*)&W_sm[(u + 64 * d) * LSTM_WSTRIDE + k4];
#pragma unroll
                for (int s = 0; s < 8; s++) {
                    float4 h4 = *(const float4*)&h_sm[(sbase + s) * H + k4];
#pragma unroll
                    for (int d = 0; d < 4; d++) {
                        acc[s][d] = fmaf(h4.x, w4[d].x, acc[s][d]);
                        acc[s][d] = fmaf(h4.y, w4[d].y, acc[s][d]);
                        acc[s][d] = fmaf(h4.z, w4[d].z, acc[s][d]);
                        acc[s][d] = fmaf(h4.w, w4[d].w, acc[s][d]);
                    }
                }
            }
#pragma unroll
            for (int s = 0; s < 8; s++) {
                float ig = sigf(acc[s][0]);
                float fg = sigf(acc[s][1]);
                float gg = tanh_fast(acc[s][2]);
                float og = sigf(acc[s][3]);
                float c = (uh == 0) ? c0[s] : c1[s];
                c = fg * c + ig * gg;
                float h = og * tanh_fast(c);
                if (uh == 0) { c0[s] = c; hn0[s] = h; }
                else         { c1[s] = c; hn1[s] = h; }
            }
        }
        __syncwarp();
#pragma unroll
        for (int s = 0; s < 8; s++) {
            h_sm[(sbase + s) * H + lane]      = hn0[s];
            h_sm[(sbase + s) * H + lane + 32] = hn1[s];
        }
        __syncwarp();
    }

#pragma unroll
    for (int s = 0; s < 8; s++) {
        int gs = s0 + sbase + s;
        if (gs < N) {
            hout[gs * H + lane]      = h_sm[(sbase + s) * H + lane];
            hout[gs * H + lane + 32] = h_sm[(sbase + s) * H + lane + 32];
        }
    }
}

// ---------------- edge scatter kernels (atomics) ----------------
// 16 threads per edge, each handles 4 features (float4 gather, 4 RED.32).
__global__ void edge_ss_kernel(const int* __restrict__ src, const int* __restrict__ dst) {
    int idx = blockIdx.x * blockDim.x + threadIdx.x;
    if (idx >= E_SS * 16) return;
    int e = idx >> 4, q = (idx & 15) << 2;
    int s = src[e], d = dst[e];
    float4 hv = *(const float4*)&g_hs[s * H + q];
    float* o1 = &g_afwd[d * H + q];
    atomicAdd(o1 + 0, hv.x); atomicAdd(o1 + 1, hv.y);
    atomicAdd(o1 + 2, hv.z); atomicAdd(o1 + 3, hv.w);
    float4 hv2 = *(const float4*)&g_hs[d * H + q];
    float* o2 = &g_arev[s * H + q];
    atomicAdd(o2 + 0, hv2.x); atomicAdd(o2 + 1, hv2.y);
    atomicAdd(o2 + 2, hv2.z); atomicAdd(o2 + 3, hv2.w);
    if (q == 0) {
        atomicAdd(&g_cntf[d], 1);
        atomicAdd(&g_cntr[s], 1);
    }
}

__global__ void edge_rs_kernel(const int* __restrict__ src, const int* __restrict__ dst) {
    int idx = blockIdx.x * blockDim.x + threadIdx.x;
    if (idx >= E_RS * 16) return;
    int e = idx >> 4, q = (idx & 15) << 2;
    int s = src[e], d = dst[e];
    float4 hv = *(const float4*)&g_hr[s * H + q];
    float* o1 = &g_ars[d * H + q];
    atomicAdd(o1 + 0, hv.x); atomicAdd(o1 + 1, hv.y);
    atomicAdd(o1 + 2, hv.z); atomicAdd(o1 + 3, hv.w);
    if (q == 0) atomicAdd(&g_cntrs[d], 1);
}

// ---------------- fused finalize ----------------
// store_h[u] = relu( hs[u] + 0.5*( btot[u] + hs.(W_self+Wr_rs)[u]
//              + vf.W_s2d[u] + vr.W_d2s[u] + va.Wl_rs[u] ) )
// where vf = (1-a)*afwd/cnt, vr = a*arev/cnt, va = ars/cnt,
// btot = b_self + bl_rs + (1-a)b_s2d + a*b_d2s.
// out = store_h @ Wf.T + bf
#define FIN_NODES 16
#define FIN_THREADS 1024
#define FIN_WS 65
#define FIN_SMEM_FLOATS (5 * H * FIN_WS + FIN_NODES * 4 * H + FIN_NODES * H + 2 * H)

__global__ __launch_bounds__(FIN_THREADS, 1)
void finalize_kernel(const float* __restrict__ W_s2d, const float* __restrict__ b_s2d,
                     const float* __restrict__ W_d2s, const float* __restrict__ b_d2s,
                     const float* __restrict__ W_self, const float* __restrict__ b_self,
                     const float* __restrict__ Wl_rs, const float* __restrict__ bl_rs,
                     const float* __restrict__ Wr_rs,
                     const float* __restrict__ Wf, const float* __restrict__ bf,
                     float* __restrict__ out)
{
    extern __shared__ float smem[];
    float* Wsum = smem;                    // 64 x 65 : W_self + Wr_rs
    float* Wa   = Wsum + H * FIN_WS;       // 64 x 65 : W_s2d
    float* Wb   = Wa + H * FIN_WS;         // 64 x 65 : W_d2s
    float* Wc   = Wb + H * FIN_WS;         // 64 x 65 : Wl_rs
    float* Wfo  = Wc + H * FIN_WS;         // 64 x 65 : Wf
    float* vec  = Wfo + H * FIN_WS;        // 16 x 4 x 64
    float* shm  = vec + FIN_NODES * 4 * H; // 16 x 64
    float* btot = shm + FIN_NODES * H;     // 64
    float* bfv  = btot + H;                // 64

    const int tid = threadIdx.x;
    const int n0 = blockIdx.x * FIN_NODES;

    for (int i = tid; i < H * H; i += FIN_THREADS) {
        int r = i >> 6, c = i & 63;
        Wsum[r * FIN_WS + c] = W_self[i] + Wr_rs[i];
        Wa[r * FIN_WS + c]   = W_s2d[i];
        Wb[r * FIN_WS + c]   = W_d2s[i];
        Wc[r * FIN_WS + c]   = Wl_rs[i];
        Wfo[r * FIN_WS + c]  = Wf[i];
    }
    if (tid < H) {
        btot[tid] = b_self[tid] + bl_rs[tid]
                  + (1.f - ALPHA) * b_s2d[tid] + ALPHA * b_d2s[tid];
        bfv[tid] = bf[tid];
    }
    // stage per-node vectors
    for (int i = tid; i < FIN_NODES * 4 * H; i += FIN_THREADS) {
        int n = i >> 8, v = (i >> 6) & 3, k = i & 63;
        int node = n0 + n;
        float val = 0.f;
        if (node < NSTORE) {
            if (v == 0) val = g_hs[node * H + k];
            else if (v == 1) {
                float cnt = (float)max(g_cntf[node], 1);
                val = (1.f - ALPHA) * g_afwd[node * H + k] / cnt;
            } else if (v == 2) {
                float cnt = (float)max(g_cntr[node], 1);
                val = ALPHA * g_arev[node * H + k] / cnt;
            } else {
                float cnt = (float)max(g_cntrs[node], 1);
                val = g_ars[node * H + k] / cnt;
            }
        }
        vec[i] = val;
    }
    __syncthreads();

    const int n = tid >> 6, u = tid & 63;
    const float* v0 = &vec[(n * 4 + 0) * H];
    const float* v1 = &vec[(n * 4 + 1) * H];
    const float* v2 = &vec[(n * 4 + 2) * H];
    const float* v3 = &vec[(n * 4 + 3) * H];

    float acc = btot[u];
#pragma unroll 8
    for (int k = 0; k < H; k++) {
        acc = fmaf(v0[k], Wsum[u * FIN_WS + k], acc);
        acc = fmaf(v1[k], Wa[u * FIN_WS + k], acc);
        acc = fmaf(v2[k], Wb[u * FIN_WS + k], acc);
        acc = fmaf(v3[k], Wc[u * FIN_WS + k], acc);
    }
    float sh = fmaxf(0.f, v0[u] + 0.5f * acc);
    shm[n * H + u] = sh;
    __syncthreads();

    float acc2 = bfv[u];  // u plays the role of output index o
#pragma unroll 8
    for (int k = 0; k < H; k++)
        acc2 = fmaf(Wfo[u * FIN_WS + k], shm[n * H + k], acc2);

    int node = n0 + n;
    if (node < NSTORE) out[node * H + u] = acc2;
}

// ---------------- launch ----------------
extern "C" void kernel_launch(void* const* d_in, const int* in_sizes, int n_in,
                              void* d_out, int out_size)
{
    const float* x_store = (const float*)d_in[0];
    const float* x_region = (const float*)d_in[1];
    const int* ess = (const int*)d_in[2];
    const int* rs_src = (const int*)d_in[3];
    const int* rs_dst = (const int*)d_in[4];
    const float* Wih_s = (const float*)d_in[7];
    const float* Whh_s = (const float*)d_in[8];
    const float* bih_s = (const float*)d_in[9];
    const float* bhh_s = (const float*)d_in[10];
    const float* Wih_r = (const float*)d_in[11];
    const float* Whh_r = (const float*)d_in[12];
    const float* bih_r = (const float*)d_in[13];
    const float* bhh_r = (const float*)d_in[14];
    const float* W_s2d = (const float*)d_in[15];
    const float* b_s2d = (const float*)d_in[16];
    const float* W_d2s = (const float*)d_in[17];
    const float* b_d2s = (const float*)d_in[18];
    const float* W_self = (const float*)d_in[19];
    const float* b_self = (const float*)d_in[20];
    const float* Wl_rs = (const float*)d_in[21];
    const float* bl_rs = (const float*)d_in[22];
    const float* Wr_rs = (const float*)d_in[23];
    const float* Wf = (const float*)d_in[27];
    const float* bf = (const float*)d_in[28];

    float *hs_p = nullptr, *hr_p = nullptr;
    cudaGetSymbolAddress((void**)&hs_p, g_hs);
    cudaGetSymbolAddress((void**)&hr_p, g_hr);

    const size_t lstm_smem = LSTM_SMEM_FLOATS * sizeof(float);
    const size_t fin_smem = FIN_SMEM_FLOATS * sizeof(float);
    cudaFuncSetAttribute(lstm_kernel, cudaFuncAttributeMaxDynamicSharedMemorySize, (int)lstm_smem);
    cudaFuncSetAttribute(finalize_kernel, cudaFuncAttributeMaxDynamicSharedMemorySize, (int)fin_smem);

    zero_kernel<<<(NSTORE * H + 255) / 256, 256>>>();

    lstm_kernel<<<(NSTORE + LSTM_SAMP - 1) / LSTM_SAMP, LSTM_THREADS, lstm_smem>>>(
        x_store, NSTORE, Wih_s, Whh_s, bih_s, bhh_s, hs_p);
    lstm_kernel<<<(NREG + LSTM_SAMP - 1) / LSTM_SAMP, LSTM_THREADS, lstm_smem>>>(
        x_region, NREG, Wih_r, Whh_r, bih_r, bhh_r, hr_p);

    edge_ss_kernel<<<(E_SS * 16 + 255) / 256, 256>>>(ess, ess + E_SS);
    edge_rs_kernel<<<(E_RS * 16 + 255) / 256, 256>>>(rs_src, rs_dst);

    finalize_kernel<<<(NSTORE + FIN_NODES - 1) / FIN_NODES, FIN_THREADS, fin_smem>>>(
        W_s2d, b_s2d, W_d2s, b_d2s, W_self, b_self,
        Wl_rs, bl_rs, Wr_rs, Wf, bf, (float*)d_out);
}

// round 2
// speedup vs baseline: 1.0260x; 1.0260x over previous
#include <cuda_runtime.h>

#define H 64
#define TS 24
#define NSTORE 20000
#define NREG 2000
#define E_SS 640000
#define E_RS 160000
#define ALPHA 0.5f

typedef unsigned long long u64;

// ---------------- device scratch (no allocations allowed) ----------------
__device__ float g_hs[NSTORE * H];
__device__ float g_hr[NREG * H];
__device__ float g_afwd[NSTORE * H];
__device__ float g_arev[NSTORE * H];
__device__ float g_ars[NSTORE * H];
__device__ int g_cnt[3 * NSTORE];
__device__ int g_off[3 * (NSTORE + 1)];
__device__ int g_cur[3 * NSTORE];
__device__ int g_csr_fwd[E_SS];   // src ids grouped by dst
__device__ int g_csr_rev[E_SS];   // dst ids grouped by src
__device__ int g_csr_rs[E_RS];    // region src ids grouped by store dst

// ---------------- f32x2 helpers ----------------
__device__ __forceinline__ u64 ffma2(u64 a, u64 b, u64 c) {
    u64 d;
    asm("fma.rn.f32x2 %0, %1, %2, %3;" : "=l"(d) : "l"(a), "l"(b), "l"(c));
    return d;
}
__device__ __forceinline__ u64 pack2(float lo, float hi) {
    u64 r; asm("mov.b64 %0, {%1, %2};" : "=l"(r) : "f"(lo), "f"(hi)); return r;
}
__device__ __forceinline__ void unpack2(u64 v, float& lo, float& hi) {
    asm("mov.b64 {%0, %1}, %2;" : "=f"(lo), "=f"(hi) : "l"(v));
}

// ---------------- activations ----------------
__device__ __forceinline__ float sigf(float x) {
    x = fminf(fmaxf(x, -30.f), 30.f);
    return __fdividef(1.f, 1.f + __expf(-x));
}
__device__ __forceinline__ float tanh_fast(float x) {
    x = fminf(fmaxf(x, -15.f), 15.f);
    float e = __expf(-2.f * x);
    return __fdividef(1.f - e, 1.f + e);
}

// ---------------- CSR build ----------------
__global__ void zero_cnt_kernel() {
    int i = blockIdx.x * blockDim.x + threadIdx.x;
    if (i < 3 * NSTORE) g_cnt[i] = 0;
}

__global__ void count_kernel(const int* __restrict__ src, const int* __restrict__ dst,
                             const int* __restrict__ rs_dst) {
    int e = blockIdx.x * blockDim.x + threadIdx.x;
    if (e < E_SS) {
        atomicAdd(&g_cnt[dst[e]], 1);
        atomicAdd(&g_cnt[NSTORE + src[e]], 1);
    }
    if (e < E_RS) atomicAdd(&g_cnt[2 * NSTORE + rs_dst[e]], 1);
}

__global__ void scan_kernel() {
    __shared__ int sd[1024];
    const int seg = blockIdx.x;
    const int base = seg * NSTORE;
    int carry = 0;
    for (int start0 = 0; start0 < NSTORE; start0 += 1024) {
        int i = start0 + threadIdx.x;
        int v = (i < NSTORE) ? g_cnt[base + i] : 0;
        sd[threadIdx.x] = v;
        __syncthreads();
        for (int ofs = 1; ofs < 1024; ofs <<= 1) {
            int y = (threadIdx.x >= (unsigned)ofs) ? sd[threadIdx.x - ofs] : 0;
            __syncthreads();
            sd[threadIdx.x] += y;
            __syncthreads();
        }
        int incl = sd[threadIdx.x];
        if (i < NSTORE) {
            int excl = carry + incl - v;
            g_off[seg * (NSTORE + 1) + i] = excl;
            g_cur[base + i] = excl;
        }
        carry += sd[1023];
        __syncthreads();
    }
    if (threadIdx.x == 0) g_off[seg * (NSTORE + 1) + NSTORE] = carry;
}

__global__ void scatter_kernel(const int* __restrict__ src, const int* __restrict__ dst,
                               const int* __restrict__ rs_src, const int* __restrict__ rs_dst) {
    int e = blockIdx.x * blockDim.x + threadIdx.x;
    if (e < E_SS) {
        int s = src[e], d = dst[e];
        g_csr_fwd[atomicAdd(&g_cur[d], 1)] = s;
        g_csr_rev[atomicAdd(&g_cur[NSTORE + s], 1)] = d;
    }
    if (e < E_RS) {
        g_csr_rs[atomicAdd(&g_cur[2 * NSTORE + rs_dst[e]], 1)] = rs_src[e];
    }
}

// ---------------- gather (mean) ----------------
// Warp per (segment, node). Lane owns feature pair (2*lane, 2*lane+1).
#define GATHER_WARPS 8
__global__ __launch_bounds__(256)
void gather_kernel() {
    int gw = blockIdx.x * GATHER_WARPS + (threadIdx.x >> 5);
    int lane = threadIdx.x & 31;
    int seg, node;
    if (gw < NSTORE)            { seg = 0; node = gw; }
    else if (gw < 2 * NSTORE)   { seg = 1; node = gw - NSTORE; }
    else if (gw < 3 * NSTORE)   { seg = 2; node = gw - 2 * NSTORE; }
    else return;

    const int* off = &g_off[seg * (NSTORE + 1)];
    int start = off[node], end = off[node + 1];
    const int* lst = (seg == 0) ? g_csr_fwd : (seg == 1) ? g_csr_rev : g_csr_rs;
    const float* feat = (seg == 2) ? g_hr : g_hs;

    float ax = 0.f, ay = 0.f;
    for (int e = start; e < end; e++) {
        int nid = __ldg(&lst[e]);                       // broadcast
        float2 v = *(const float2*)&feat[nid * H + lane * 2];
        ax += v.x; ay += v.y;
    }
    float inv = (end > start) ? __fdividef(1.f, (float)(end - start)) : 0.f;
    float* out = (seg == 0) ? g_afwd : (seg == 1) ? g_arev : g_ars;
    *(float2*)&out[node * H + lane * 2] = make_float2(ax * inv, ay * inv);
}

// ---------------- LSTM kernel (f32x2 packed FFMA) ----------------
// Block: 256 threads = 8 warps, 8 samples/warp. Lane l -> units l, l+32.
// Whh in smem (stride 68, conflict-free LDS.128); h in per-warp smem rows.
// k-dimension packed in f32x2 pairs: even-k in lo half, odd-k in hi half.
#define LSTM_WSTRIDE 68
#define LSTM_SAMP 64
#define LSTM_THREADS 256
#define LSTM_SMEM_FLOATS (256 * LSTM_WSTRIDE + LSTM_SAMP * H + LSTM_SAMP * TS + 256 + 256)

__global__ __launch_bounds__(LSTM_THREADS, 2)
void lstm_kernel(const float* __restrict__ x, int N,
                 const float* __restrict__ Wih,
                 const float* __restrict__ Whh,
                 const float* __restrict__ bih,
                 const float* __restrict__ bhh,
                 float* __restrict__ hout)
{
    extern __shared__ float smem[];
    float* W_sm   = smem;                                 // 256 x 68
    float* h_sm   = W_sm + 256 * LSTM_WSTRIDE;            // 64 x 64
    float* x_sm   = h_sm + LSTM_SAMP * H;                 // 64 x 24
    float* win_sm = x_sm + LSTM_SAMP * TS;                // 256
    float* b_sm   = win_sm + 256;                         // 256

    const int tid = threadIdx.x;
    const int s0 = blockIdx.x * LSTM_SAMP;

    for (int i = tid; i < 256 * H; i += LSTM_THREADS) {
        int r = i >> 6, c = i & 63;
        W_sm[r * LSTM_WSTRIDE + c] = Whh[i];
    }
    for (int i = tid; i < 256; i += LSTM_THREADS) {
        win_sm[i] = Wih[i];
        b_sm[i] = bih[i] + bhh[i];
    }
    for (int i = tid; i < LSTM_SAMP * TS; i += LSTM_THREADS) {
        long gi = (long)s0 * TS + i;
        x_sm[i] = (gi < (long)N * TS) ? x[gi] : 0.f;
    }
    for (int i = tid; i < LSTM_SAMP * H; i += LSTM_THREADS) h_sm[i] = 0.f;
    __syncthreads();

    const int warp = tid >> 5, lane = tid & 31;
    const int sbase = warp * 8;

    float c0[8], c1[8];
#pragma unroll
    for (int s = 0; s < 8; s++) { c0[s] = 0.f; c1[s] = 0.f; }

    for (int t = 0; t < TS; t++) {
        float xt[8];
#pragma unroll
        for (int s = 0; s < 8; s++) xt[s] = x_sm[(sbase + s) * TS + t];

        float hn0[8], hn1[8];
#pragma unroll
        for (int uh = 0; uh < 2; uh++) {
            const int u = lane + 32 * uh;
            u64 acc2[8][4];
#pragma unroll
            for (int d = 0; d < 4; d++) {
                int j = u + 64 * d;
                float w = win_sm[j], b = b_sm[j];
#pragma unroll
                for (int s = 0; s < 8; s++)
                    acc2[s][d] = pack2(fmaf(xt[s], w, b), 0.f);
            }
#pragma unroll 2
            for (int k4 = 0; k4 < H; k4 += 4) {
                u64 w2[4][2];
#pragma unroll
                for (int d = 0; d < 4; d++) {
                    ulonglong2 ww = *(const ulonglong2*)&W_sm[(u + 64 * d) * LSTM_WSTRIDE + k4];
                    w2[d][0] = ww.x; w2[d][1] = ww.y;
                }
#pragma unroll
                for (int s = 0; s < 8; s++) {
                    ulonglong2 hh = *(const ulonglong2*)&h_sm[(sbase + s) * H + k4];
#pragma unroll
                    for (int d = 0; d < 4; d++)
                        acc2[s][d] = ffma2(hh.x, w2[d][0], acc2[s][d]);
#pragma unroll
                    for (int d = 0; d < 4; d++)
                        acc2[s][d] = ffma2(hh.y, w2[d][1], acc2[s][d]);
                }
            }
#pragma unroll
            for (int s = 0; s < 8; s++) {
                float g[4];
#pragma unroll
                for (int d = 0; d < 4; d++) {
                    float lo, hi; unpack2(acc2[s][d], lo, hi);
                    g[d] = lo + hi;
                }
                float ig = sigf(g[0]);
                float fg = sigf(g[1]);
                float gg = tanh_fast(g[2]);
                float og = sigf(g[3]);
                float c = (uh == 0) ? c0[s] : c1[s];
                c = fg * c + ig * gg;
                float h = og * tanh_fast(c);
                if (uh == 0) { c0[s] = c; hn0[s] = h; }
                else         { c1[s] = c; hn1[s] = h; }
            }
        }
        __syncwarp();
#pragma unroll
        for (int s = 0; s < 8; s++) {
            h_sm[(sbase + s) * H + lane]      = hn0[s];
            h_sm[(sbase + s) * H + lane + 32] = hn1[s];
        }
        __syncwarp();
    }

#pragma unroll
    for (int s = 0; s < 8; s++) {
        int gs = s0 + sbase + s;
        if (gs < N) {
            hout[gs * H + lane]      = h_sm[(sbase + s) * H + lane];
            hout[gs * H + lane + 32] = h_sm[(sbase + s) * H + lane + 32];
        }
    }
}

// ---------------- fused finalize ----------------
#define FIN_NODES 16
#define FIN_THREADS 1024
#define FIN_WS 65
#define FIN_SMEM_FLOATS (5 * H * FIN_WS + FIN_NODES * 4 * H + FIN_NODES * H + 2 * H)

__global__ __launch_bounds__(FIN_THREADS, 1)
void finalize_kernel(const float* __restrict__ W_s2d, const float* __restrict__ b_s2d,
                     const float* __restrict__ W_d2s, const float* __restrict__ b_d2s,
                     const float* __restrict__ W_self, const float* __restrict__ b_self,
                     const float* __restrict__ Wl_rs, const float* __restrict__ bl_rs,
                     const float* __restrict__ Wr_rs,
                     const float* __restrict__ Wf, const float* __restrict__ bf,
                     float* __restrict__ out)
{
    extern __shared__ float smem[];
    float* Wsum = smem;                    // W_self + Wr_rs
    float* Wa   = Wsum + H * FIN_WS;       // W_s2d
    float* Wb   = Wa + H * FIN_WS;         // W_d2s
    float* Wc   = Wb + H * FIN_WS;         // Wl_rs
    float* Wfo  = Wc + H * FIN_WS;         // Wf
    float* vec  = Wfo + H * FIN_WS;        // 16 x 4 x 64
    float* shm  = vec + FIN_NODES * 4 * H; // 16 x 64
    float* btot = shm + FIN_NODES * H;     // 64
    float* bfv  = btot + H;                // 64

    const int tid = threadIdx.x;
    const int n0 = blockIdx.x * FIN_NODES;

    for (int i = tid; i < H * H; i += FIN_THREADS) {
        int r = i >> 6, c = i & 63;
        Wsum[r * FIN_WS + c] = W_self[i] + Wr_rs[i];
        Wa[r * FIN_WS + c]   = W_s2d[i];
        Wb[r * FIN_WS + c]   = W_d2s[i];
        Wc[r * FIN_WS + c]   = Wl_rs[i];
        Wfo[r * FIN_WS + c]  = Wf[i];
    }
    if (tid < H) {
        btot[tid] = b_self[tid] + bl_rs[tid]
                  + (1.f - ALPHA) * b_s2d[tid] + ALPHA * b_d2s[tid];
        bfv[tid] = bf[tid];
    }
    for (int i = tid; i < FIN_NODES * 4 * H; i += FIN_THREADS) {
        int n = i >> 8, v = (i >> 6) & 3, k = i & 63;
        int node = n0 + n;
        float val = 0.f;
        if (node < NSTORE) {
            if (v == 0)      val = g_hs[node * H + k];
            else if (v == 1) val = (1.f - ALPHA) * g_afwd[node * H + k];
            else if (v == 2) val = ALPHA * g_arev[node * H + k];
            else             val = g_ars[node * H + k];
        }
        vec[i] = val;
    }
    __syncthreads();

    const int n = tid >> 6, u = tid & 63;
    const float* v0 = &vec[(n * 4 + 0) * H];
    const float* v1 = &vec[(n * 4 + 1) * H];
    const float* v2 = &vec[(n * 4 + 2) * H];
    const float* v3 = &vec[(n * 4 + 3) * H];

    float acc = btot[u];
#pragma unroll 8
    for (int k = 0; k < H; k++) {
        acc = fmaf(v0[k], Wsum[u * FIN_WS + k], acc);
        acc = fmaf(v1[k], Wa[u * FIN_WS + k], acc);
        acc = fmaf(v2[k], Wb[u * FIN_WS + k], acc);
        acc = fmaf(v3[k], Wc[u * FIN_WS + k], acc);
    }
    float sh = fmaxf(0.f, v0[u] + 0.5f * acc);
    shm[n * H + u] = sh;
    __syncthreads();

    float acc2 = bfv[u];
#pragma unroll 8
    for (int k = 0; k < H; k++)
        acc2 = fmaf(Wfo[u * FIN_WS + k], shm[n * H + k], acc2);

    int node = n0 + n;
    if (node < NSTORE) out[node * H + u] = acc2;
}

// ---------------- launch ----------------
extern "C" void kernel_launch(void* const* d_in, const int* in_sizes, int n_in,
                              void* d_out, int out_size)
{
    const float* x_store  = (const float*)d_in[0];
    const float* x_region = (const float*)d_in[1];
    const int* ess    = (const int*)d_in[2];
    const int* rs_src = (const int*)d_in[3];
    const int* rs_dst = (const int*)d_in[4];
    const float* Wih_s = (const float*)d_in[7];
    const float* Whh_s = (const float*)d_in[8];
    const float* bih_s = (const float*)d_in[9];
    const float* bhh_s = (const float*)d_in[10];
    const float* Wih_r = (const float*)d_in[11];
    const float* Whh_r = (const float*)d_in[12];
    const float* bih_r = (const float*)d_in[13];
    const float* bhh_r = (const float*)d_in[14];
    const float* W_s2d = (const float*)d_in[15];
    const float* b_s2d = (const float*)d_in[16];
    const float* W_d2s = (const float*)d_in[17];
    const float* b_d2s = (const float*)d_in[18];
    const float* W_self = (const float*)d_in[19];
    const float* b_self = (const float*)d_in[20];
    const float* Wl_rs = (const float*)d_in[21];
    const float* bl_rs = (const float*)d_in[22];
    const float* Wr_rs = (const float*)d_in[23];
    const float* Wf = (const float*)d_in[27];
    const float* bf = (const float*)d_in[28];

    float *hs_p = nullptr, *hr_p = nullptr;
    cudaGetSymbolAddress((void**)&hs_p, g_hs);
    cudaGetSymbolAddress((void**)&hr_p, g_hr);

    const size_t lstm_smem = LSTM_SMEM_FLOATS * sizeof(float);
    const size_t fin_smem = FIN_SMEM_FLOATS * sizeof(float);
    cudaFuncSetAttribute(lstm_kernel, cudaFuncAttributeMaxDynamicSharedMemorySize, (int)lstm_smem);
    cudaFuncSetAttribute(finalize_kernel, cudaFuncAttributeMaxDynamicSharedMemorySize, (int)fin_smem);

    // CSR build (independent of LSTM)
    zero_cnt_kernel<<<(3 * NSTORE + 255) / 256, 256>>>();
    count_kernel<<<(E_SS + 255) / 256, 256>>>(ess, ess + E_SS, rs_dst);
    scan_kernel<<<3, 1024>>>();
    scatter_kernel<<<(E_SS + 255) / 256, 256>>>(ess, ess + E_SS, rs_src, rs_dst);

    // LSTMs
    lstm_kernel<<<(NSTORE + LSTM_SAMP - 1) / LSTM_SAMP, LSTM_THREADS, lstm_smem>>>(
        x_store, NSTORE, Wih_s, Whh_s, bih_s, bhh_s, hs_p);
    lstm_kernel<<<(NREG + LSTM_SAMP - 1) / LSTM_SAMP, LSTM_THREADS, lstm_smem>>>(
        x_region, NREG, Wih_r, Whh_r, bih_r, bhh_r, hr_p);

    // Mean aggregation via CSR gather
    gather_kernel<<<(3 * NSTORE + GATHER_WARPS - 1) / GATHER_WARPS, 256>>>();

    finalize_kernel<<<(NSTORE + FIN_NODES - 1) / FIN_NODES, FIN_THREADS, fin_smem>>>(
        W_s2d, b_s2d, W_d2s, b_d2s, W_self, b_self,
        Wl_rs, bl_rs, Wr_rs, Wf, bf, (float*)d_out);
}

// round 3
// speedup vs baseline: 1.0267x; 1.0007x over previous
#include <cuda_runtime.h>

#define H 64
#define TS 24
#define NSTORE 20000
#define NREG 2000
#define E_SS 640000
#define E_RS 160000
#define ALPHA 0.5f

typedef unsigned long long u64;

// ---------------- device scratch (no allocations allowed) ----------------
__device__ float g_hs[NSTORE * H];
__device__ float g_hr[NREG * H];
__device__ float g_afwd[NSTORE * H];
__device__ float g_arev[NSTORE * H];
__device__ float g_ars[NSTORE * H];
__device__ int g_cnt[3 * NSTORE];
__device__ int g_off[3 * (NSTORE + 1)];
__device__ int g_cur[3 * NSTORE];
__device__ int g_csr_fwd[E_SS];   // src ids grouped by dst
__device__ int g_csr_rev[E_SS];   // dst ids grouped by src
__device__ int g_csr_rs[E_RS];    // region src ids grouped by store dst

// ---------------- f32x2 helpers ----------------
__device__ __forceinline__ u64 ffma2(u64 a, u64 b, u64 c) {
    u64 d;
    asm("fma.rn.f32x2 %0, %1, %2, %3;" : "=l"(d) : "l"(a), "l"(b), "l"(c));
    return d;
}
__device__ __forceinline__ u64 pack2(float lo, float hi) {
    u64 r; asm("mov.b64 %0, {%1, %2};" : "=l"(r) : "f"(lo), "f"(hi)); return r;
}
__device__ __forceinline__ void unpack2(u64 v, float& lo, float& hi) {
    asm("mov.b64 {%0, %1}, %2;" : "=f"(lo), "=f"(hi) : "l"(v));
}

// ---------------- activations ----------------
__device__ __forceinline__ float sigf(float x) {
    x = fminf(fmaxf(x, -30.f), 30.f);
    return __fdividef(1.f, 1.f + __expf(-x));
}
__device__ __forceinline__ float tanh_fast(float x) {
    x = fminf(fmaxf(x, -15.f), 15.f);
    float e = __expf(-2.f * x);
    return __fdividef(1.f - e, 1.f + e);
}

// ---------------- CSR build ----------------
__global__ void zero_cnt_kernel() {
    int i = blockIdx.x * blockDim.x + threadIdx.x;
    if (i < 3 * NSTORE) g_cnt[i] = 0;
}

__global__ void count_kernel(const int* __restrict__ src, const int* __restrict__ dst,
                             const int* __restrict__ rs_dst) {
    int e = blockIdx.x * blockDim.x + threadIdx.x;
    if (e < E_SS) {
        atomicAdd(&g_cnt[dst[e]], 1);
        atomicAdd(&g_cnt[NSTORE + src[e]], 1);
    }
    if (e < E_RS) atomicAdd(&g_cnt[2 * NSTORE + rs_dst[e]], 1);
}

__global__ void scan_kernel() {
    __shared__ int sd[1024];
    const int seg = blockIdx.x;
    const int base = seg * NSTORE;
    int carry = 0;
    for (int start0 = 0; start0 < NSTORE; start0 += 1024) {
        int i = start0 + threadIdx.x;
        int v = (i < NSTORE) ? g_cnt[base + i] : 0;
        sd[threadIdx.x] = v;
        __syncthreads();
        for (int ofs = 1; ofs < 1024; ofs <<= 1) {
            int y = (threadIdx.x >= (unsigned)ofs) ? sd[threadIdx.x - ofs] : 0;
            __syncthreads();
            sd[threadIdx.x] += y;
            __syncthreads();
        }
        int incl = sd[threadIdx.x];
        if (i < NSTORE) {
            int excl = carry + incl - v;
            g_off[seg * (NSTORE + 1) + i] = excl;
            g_cur[base + i] = excl;
        }
        carry += sd[1023];
        __syncthreads();
    }
    if (threadIdx.x == 0) g_off[seg * (NSTORE + 1) + NSTORE] = carry;
}

__global__ void scatter_kernel(const int* __restrict__ src, const int* __restrict__ dst,
                               const int* __restrict__ rs_src, const int* __restrict__ rs_dst) {
    int e = blockIdx.x * blockDim.x + threadIdx.x;
    if (e < E_SS) {
        int s = src[e], d = dst[e];
        g_csr_fwd[atomicAdd(&g_cur[d], 1)] = s;
        g_csr_rev[atomicAdd(&g_cur[NSTORE + s], 1)] = d;
    }
    if (e < E_RS) {
        g_csr_rs[atomicAdd(&g_cur[2 * NSTORE + rs_dst[e]], 1)] = rs_src[e];
    }
}

// ---------------- gather (mean) ----------------
// Warp per (segment, node). Lane owns feature pair (2*lane, 2*lane+1).
#define GATHER_WARPS 8
__global__ __launch_bounds__(256)
void gather_kernel() {
    int gw = blockIdx.x * GATHER_WARPS + (threadIdx.x >> 5);
    int lane = threadIdx.x & 31;
    int seg, node;
    if (gw < NSTORE)            { seg = 0; node = gw; }
    else if (gw < 2 * NSTORE)   { seg = 1; node = gw - NSTORE; }
    else if (gw < 3 * NSTORE)   { seg = 2; node = gw - 2 * NSTORE; }
    else return;

    const int* off = &g_off[seg * (NSTORE + 1)];
    int start = off[node], end = off[node + 1];
    const int* lst = (seg == 0) ? g_csr_fwd : (seg == 1) ? g_csr_rev : g_csr_rs;
    const float* feat = (seg == 2) ? g_hr : g_hs;

    float ax = 0.f, ay = 0.f;
    for (int e = start; e < end; e++) {
        int nid = __ldg(&lst[e]);                       // broadcast
        float2 v = *(const float2*)&feat[nid * H + lane * 2];
        ax += v.x; ay += v.y;
    }
    float inv = (end > start) ? __fdividef(1.f, (float)(end - start)) : 0.f;
    float* out = (seg == 0) ? g_afwd : (seg == 1) ? g_arev : g_ars;
    *(float2*)&out[node * H + lane * 2] = make_float2(ax * inv, ay * inv);
}

// ---------------- LSTM kernel (f32x2 packed FFMA) ----------------
// Block: 256 threads = 8 warps, 8 samples/warp. Lane l -> units l, l+32.
// Whh in smem (stride 68, conflict-free LDS.128); h in per-warp smem rows.
// k-dimension packed in f32x2 pairs: even-k in lo half, odd-k in hi half.
#define LSTM_WSTRIDE 68
#define LSTM_SAMP 64
#define LSTM_THREADS 256
#define LSTM_SMEM_FLOATS (256 * LSTM_WSTRIDE + LSTM_SAMP * H + LSTM_SAMP * TS + 256 + 256)

__global__ __launch_bounds__(LSTM_THREADS, 2)
void lstm_kernel(const float* __restrict__ x, int N,
                 const float* __restrict__ Wih,
                 const float* __restrict__ Whh,
                 const float* __restrict__ bih,
                 const float* __restrict__ bhh,
                 float* __restrict__ hout)
{
    extern __shared__ float smem[];
    float* W_sm   = smem;                                 // 256 x 68
    float* h_sm   = W_sm + 256 * LSTM_WSTRIDE;            // 64 x 64
    float* x_sm   = h_sm + LSTM_SAMP * H;                 // 64 x 24
    float* win_sm = x_sm + LSTM_SAMP * TS;                // 256
    float* b_sm   = win_sm + 256;                         // 256

    const int tid = threadIdx.x;
    const int s0 = blockIdx.x * LSTM_SAMP;

    for (int i = tid; i < 256 * H; i += LSTM_THREADS) {
        int r = i >> 6, c = i & 63;
        W_sm[r * LSTM_WSTRIDE + c] = Whh[i];
    }
    for (int i = tid; i < 256; i += LSTM_THREADS) {
        win_sm[i] = Wih[i];
        b_sm[i] = bih[i] + bhh[i];
    }
    for (int i = tid; i < LSTM_SAMP * TS; i += LSTM_THREADS) {
        long gi = (long)s0 * TS + i;
        x_sm[i] = (gi < (long)N * TS) ? x[gi] : 0.f;
    }
    for (int i = tid; i < LSTM_SAMP * H; i += LSTM_THREADS) h_sm[i] = 0.f;
    __syncthreads();

    const int warp = tid >> 5, lane = tid & 31;
    const int sbase = warp * 8;

    float c0[8], c1[8];
#pragma unroll
    for (int s = 0; s < 8; s++) { c0[s] = 0.f; c1[s] = 0.f; }

    for (int t = 0; t < TS; t++) {
        float xt[8];
#pragma unroll
        for (int s = 0; s < 8; s++) xt[s] = x_sm[(sbase + s) * TS + t];

        float hn0[8], hn1[8];
#pragma unroll
        for (int uh = 0; uh < 2; uh++) {
            const int u = lane + 32 * uh;
            u64 acc2[8][4];
#pragma unroll
            for (int d = 0; d < 4; d++) {
                int j = u + 64 * d;
                float w = win_sm[j], b = b_sm[j];
#pragma unroll
                for (int s = 0; s < 8; s++)
                    acc2[s][d] = pack2(fmaf(xt[s], w, b), 0.f);
            }
#pragma unroll 2
            for (int k4 = 0; k4 < H; k4 += 4) {
                u64 w2[4][2];
#pragma unroll
                for (int d = 0; d < 4; d++) {
                    ulonglong2 ww = *(const ulonglong2*)&W_sm[(u + 64 * d) * LSTM_WSTRIDE + k4];
                    w2[d][0] = ww.x; w2[d][1] = ww.y;
                }
#pragma unroll
                for (int s = 0; s < 8; s++) {
                    ulonglong2 hh = *(const ulonglong2*)&h_sm[(sbase + s) * H + k4];
#pragma unroll
                    for (int d = 0; d < 4; d++)
                        acc2[s][d] = ffma2(hh.x, w2[d][0], acc2[s][d]);
#pragma unroll
                    for (int d = 0; d < 4; d++)
                        acc2[s][d] = ffma2(hh.y, w2[d][1], acc2[s][d]);
                }
            }
#pragma unroll
            for (int s = 0; s < 8; s++) {
                float g[4];
#pragma unroll
                for (int d = 0; d < 4; d++) {
                    float lo, hi; unpack2(acc2[s][d], lo, hi);
                    g[d] = lo + hi;
                }
                float ig = sigf(g[0]);
                float fg = sigf(g[1]);
                float gg = tanh_fast(g[2]);
                float og = sigf(g[3]);
                float c = (uh == 0) ? c0[s] : c1[s];
                c = fg * c + ig * gg;
                float h = og * tanh_fast(c);
                if (uh == 0) { c0[s] = c; hn0[s] = h; }
                else         { c1[s] = c; hn1[s] = h; }
            }
        }
        __syncwarp();
#pragma unroll
        for (int s = 0; s < 8; s++) {
            h_sm[(sbase + s) * H + lane]      = hn0[s];
            h_sm[(sbase + s) * H + lane + 32] = hn1[s];
        }
        __syncwarp();
    }

#pragma unroll
    for (int s = 0; s < 8; s++) {
        int gs = s0 + sbase + s;
        if (gs < N) {
            hout[gs * H + lane]      = h_sm[(sbase + s) * H + lane];
            hout[gs * H + lane + 32] = h_sm[(sbase + s) * H + lane + 32];
        }
    }
}

// ---------------- fused finalize ----------------
#define FIN_NODES 16
#define FIN_THREADS 1024
#define FIN_WS 65
#define FIN_SMEM_FLOATS (5 * H * FIN_WS + FIN_NODES * 4 * H + FIN_NODES * H + 2 * H)

__global__ __launch_bounds__(FIN_THREADS, 1)
void finalize_kernel(const float* __restrict__ W_s2d, const float* __restrict__ b_s2d,
                     const float* __restrict__ W_d2s, const float* __restrict__ b_d2s,
                     const float* __restrict__ W_self, const float* __restrict__ b_self,
                     const float* __restrict__ Wl_rs, const float* __restrict__ bl_rs,
                     const float* __restrict__ Wr_rs,
                     const float* __restrict__ Wf, const float* __restrict__ bf,
                     float* __restrict__ out)
{
    extern __shared__ float smem[];
    float* Wsum = smem;                    // W_self + Wr_rs
    float* Wa   = Wsum + H * FIN_WS;       // W_s2d
    float* Wb   = Wa + H * FIN_WS;         // W_d2s
    float* Wc   = Wb + H * FIN_WS;         // Wl_rs
    float* Wfo  = Wc + H * FIN_WS;         // Wf
    float* vec  = Wfo + H * FIN_WS;        // 16 x 4 x 64
    float* shm  = vec + FIN_NODES * 4 * H; // 16 x 64
    float* btot = shm + FIN_NODES * H;     // 64
    float* bfv  = btot + H;                // 64

    const int tid = threadIdx.x;
    const int n0 = blockIdx.x * FIN_NODES;

    for (int i = tid; i < H * H; i += FIN_THREADS) {
        int r = i >> 6, c = i & 63;
        Wsum[r * FIN_WS + c] = W_self[i] + Wr_rs[i];
        Wa[r * FIN_WS + c]   = W_s2d[i];
        Wb[r * FIN_WS + c]   = W_d2s[i];
        Wc[r * FIN_WS + c]   = Wl_rs[i];
        Wfo[r * FIN_WS + c]  = Wf[i];
    }
    if (tid < H) {
        btot[tid] = b_self[tid] + bl_rs[tid]
                  + (1.f - ALPHA) * b_s2d[tid] + ALPHA * b_d2s[tid];
        bfv[tid] = bf[tid];
    }
    for (int i = tid; i < FIN_NODES * 4 * H; i += FIN_THREADS) {
        int n = i >> 8, v = (i >> 6) & 3, k = i & 63;
        int node = n0 + n;
        float val = 0.f;
        if (node < NSTORE) {
            if (v == 0)      val = g_hs[node * H + k];
            else if (v == 1) val = (1.f - ALPHA) * g_afwd[node * H + k];
            else if (v == 2) val = ALPHA * g_arev[node * H + k];
            else             val = g_ars[node * H + k];
        }
        vec[i] = val;
    }
    __syncthreads();

    const int n = tid >> 6, u = tid & 63;
    const float* v0 = &vec[(n * 4 + 0) * H];
    const float* v1 = &vec[(n * 4 + 1) * H];
    const float* v2 = &vec[(n * 4 + 2) * H];
    const float* v3 = &vec[(n * 4 + 3) * H];

    float acc = btot[u];
#pragma unroll 8
    for (int k = 0; k < H; k++) {
        acc = fmaf(v0[k], Wsum[u * FIN_WS + k], acc);
        acc = fmaf(v1[k], Wa[u * FIN_WS + k], acc);
        acc = fmaf(v2[k], Wb[u * FIN_WS + k], acc);
        acc = fmaf(v3[k], Wc[u * FIN_WS + k], acc);
    }
    float sh = fmaxf(0.f, v0[u] + 0.5f * acc);
    shm[n * H + u] = sh;
    __syncthreads();

    float acc2 = bfv[u];
#pragma unroll 8
    for (int k = 0; k < H; k++)
        acc2 = fmaf(Wfo[u * FIN_WS + k], shm[n * H + k], acc2);

    int node = n0 + n;
    if (node < NSTORE) out[node * H + u] = acc2;
}

// ---------------- launch ----------------
extern "C" void kernel_launch(void* const* d_in, const int* in_sizes, int n_in,
                              void* d_out, int out_size)
{
    const float* x_store  = (const float*)d_in[0];
    const float* x_region = (const float*)d_in[1];
    const int* ess    = (const int*)d_in[2];
    const int* rs_src = (const int*)d_in[3];
    const int* rs_dst = (const int*)d_in[4];
    const float* Wih_s = (const float*)d_in[7];
    const float* Whh_s = (const float*)d_in[8];
    const float* bih_s = (const float*)d_in[9];
    const float* bhh_s = (const float*)d_in[10];
    const float* Wih_r = (const float*)d_in[11];
    const float* Whh_r = (const float*)d_in[12];
    const float* bih_r = (const float*)d_in[13];
    const float* bhh_r = (const float*)d_in[14];
    const float* W_s2d = (const float*)d_in[15];
    const float* b_s2d = (const float*)d_in[16];
    const float* W_d2s = (const float*)d_in[17];
    const float* b_d2s = (const float*)d_in[18];
    const float* W_self = (const float*)d_in[19];
    const float* b_self = (const float*)d_in[20];
    const float* Wl_rs = (const float*)d_in[21];
    const float* bl_rs = (const float*)d_in[22];
    const float* Wr_rs = (const float*)d_in[23];
    const float* Wf = (const float*)d_in[27];
    const float* bf = (const float*)d_in[28];

    float *hs_p = nullptr, *hr_p = nullptr;
    cudaGetSymbolAddress((void**)&hs_p, g_hs);
    cudaGetSymbolAddress((void**)&hr_p, g_hr);

    const size_t lstm_smem = LSTM_SMEM_FLOATS * sizeof(float);
    const size_t fin_smem = FIN_SMEM_FLOATS * sizeof(float);
    cudaFuncSetAttribute(lstm_kernel, cudaFuncAttributeMaxDynamicSharedMemorySize, (int)lstm_smem);
    cudaFuncSetAttribute(finalize_kernel, cudaFuncAttributeMaxDynamicSharedMemorySize, (int)fin_smem);

    // CSR build (independent of LSTM)
    zero_cnt_kernel<<<(3 * NSTORE + 255) / 256, 256>>>();
    count_kernel<<<(E_SS + 255) / 256, 256>>>(ess, ess + E_SS, rs_dst);
    scan_kernel<<<3, 1024>>>();
    scatter_kernel<<<(E_SS + 255) / 256, 256>>>(ess, ess + E_SS, rs_src, rs_dst);

    // LSTMs
    lstm_kernel<<<(NSTORE + LSTM_SAMP - 1) / LSTM_SAMP, LSTM_THREADS, lstm_smem>>>(
        x_store, NSTORE, Wih_s, Whh_s, bih_s, bhh_s, hs_p);
    lstm_kernel<<<(NREG + LSTM_SAMP - 1) / LSTM_SAMP, LSTM_THREADS, lstm_smem>>>(
        x_region, NREG, Wih_r, Whh_r, bih_r, bhh_r, hr_p);

    // Mean aggregation via CSR gather
    gather_kernel<<<(3 * NSTORE + GATHER_WARPS - 1) / GATHER_WARPS, 256>>>();

    finalize_kernel<<<(NSTORE + FIN_NODES - 1) / FIN_NODES, FIN_THREADS, fin_smem>>>(
        W_s2d, b_s2d, W_d2s, b_d2s, W_self, b_self,
        Wl_rs, bl_rs, Wr_rs, Wf, bf, (float*)d_out);
}